// round 10
// baseline (speedup 1.0000x reference)
#include <cuda_runtime.h>
#include <cuda_bf16.h>

// Problem constants
#define NN   8192
#define KK   32
#define CC   16
#define RBFN 16
#define HH   64

// Dynamic shared-memory layout (in floats).
// Total dynamic = 12,272 floats = 49,088 B; static smem = 0.
// 49,088 <= 49,152 (48 KB default cap) -> launch is legal WITHOUT
// cudaFuncSetAttribute. (R7 failed because a 128 B static array pushed
// static+dynamic to 49,216 B, 64 B over the cap -> launch error ->
// capture invalidated.)
#define OFF_RBF  0        // 32*16  = 512
#define OFF_E    512      // 32*4   = 128
#define OFF_F0N  640      // 32*16  = 512
#define OFF_F1N  1152     // 32*48  = 1536
#define OFF_H1   2688     // 32*64  = 2048
#define OFF_H2   4736     // 32*64  = 2048
#define OFF_CTR  6784     // 32*48  = 1536
#define OFF_M    8320     // 65*48  = 3120   (nb_s aliases the first 32 floats
                          //                  of this region during phases 1-2;
                          //                  M_s is first written later)
#define OFF_RED  11440    // 16*48  = 768
#define OFF_ACC0 12208    // 16
#define OFF_ACC1 12224    // 48
#define SMEM_FLOATS 12272
#define SMEM_BYTES (SMEM_FLOATS * 4)

__device__ __forceinline__ float siluf(float x) {
    return __fdividef(x, 1.0f + __expf(-x));
}
__device__ __forceinline__ float sigmf(float x) {
    return __fdividef(1.0f, 1.0f + __expf(-x));
}

__global__ __launch_bounds__(256, 4)
void gtt_kernel(const float* __restrict__ f0, const float* __restrict__ f1,
                const float* __restrict__ rbf, const float* __restrict__ gt_edge,
                const float* __restrict__ W1, const float* __restrict__ b1,
                const float* __restrict__ W2, const float* __restrict__ b2,
                const float* __restrict__ W3, const float* __restrict__ b3,
                const float* __restrict__ ln_g0, const float* __restrict__ ln_b0,
                const float* __restrict__ ln_g1, const float* __restrict__ ln_b1,
                const float* __restrict__ gate_W0, const float* __restrict__ gate_b0,
                const float* __restrict__ gate_W1, const float* __restrict__ gate_b1,
                const float* __restrict__ res_W0, const float* __restrict__ res_W1,
                const int* __restrict__ nbr_idx,
                float* __restrict__ out)
{
    extern __shared__ float sm[];
    float* rbf_s = sm + OFF_RBF;
    float* e_s   = sm + OFF_E;
    float* f0n_s = sm + OFF_F0N;
    float* f1n_s = sm + OFF_F1N;
    float* h1_s  = sm + OFF_H1;
    float* h2_s  = sm + OFF_H2;
    float* ctr_s = sm + OFF_CTR;
    float* M_s   = sm + OFF_M;
    float* red_s = sm + OFF_RED;
    float* acc0  = sm + OFF_ACC0;
    float* acc1  = sm + OFF_ACC1;
    int*   nb_s  = (int*)(sm + OFF_M);   // aliases M_s; dead before M_s is written

    const int tid = threadIdx.x;
    const int i   = blockIdx.x;

    // ---- Phase 1: node-local loads ----
    if (tid < KK) nb_s[tid] = nbr_idx[i * KK + tid];
    for (int idx = tid; idx < 512; idx += 256)
        rbf_s[idx] = rbf[i * 512 + idx];
    if (tid < 128) e_s[tid] = gt_edge[i * 128 + tid];
    if (tid < 64) { if (tid < 16) acc0[tid] = 0.f; else acc1[tid - 16] = 0.f; }
    __syncthreads();

    // ---- Phase 2: neighbor gathers ----
    for (int idx = tid; idx < 512; idx += 256) {
        int j = idx >> 4, c = idx & 15;
        f0n_s[idx] = f0[nb_s[j] * 16 + c];
    }
    for (int idx = tid; idx < 1536; idx += 256) {
        int j = idx / 48, r = idx - j * 48;
        f1n_s[idx] = f1[nb_s[j] * 48 + r];
    }
    __syncthreads();
    // nb_s no longer needed; its storage becomes M_s inside the path loop.

    // ---- Interaction paths ----
    #pragma unroll
    for (int t = 0; t < 5; t++) {
        const int dd = (t == 0 || t == 3) ? 1 : 3;   // output vector dim
        const int ot = (t == 0 || t == 3) ? 0 : 1;   // which output accumulator
        const int md = 16 * dd;
        const float* W1t = W1 + t * RBFN * HH;
        const float* b1t = b1 + t * HH;
        const float* W2t = W2 + t * HH * HH;
        const float* b2t = b2 + t * HH;
        const float* W3t = W3 + t * HH * 256;
        const float* b3t = b3 + t * 256;

        // ---- h1 = silu(rbf @ W1 + b1) : [32 x 64] ----
        {
            int h = tid & 63, j0 = tid >> 6;   // thread owns column h, rows j0+4k
            float s[8];
            float bb = b1t[h];
            #pragma unroll
            for (int k = 0; k < 8; k++) s[k] = bb;
            #pragma unroll
            for (int r = 0; r < 16; r++) {
                float w = W1t[r * 64 + h];       // coalesced, L2-resident
                #pragma unroll
                for (int k = 0; k < 8; k++)
                    s[k] = fmaf(rbf_s[(j0 + 4 * k) * 16 + r], w, s[k]);
            }
            #pragma unroll
            for (int k = 0; k < 8; k++)
                h1_s[(j0 + 4 * k) * 64 + h] = siluf(s[k]);
        }
        __syncthreads();

        // ---- h2 = silu(h1 @ W2 + b2) : [32 x 64] ----
        // W2 read directly from global: for fixed r, lanes span consecutive h
        // -> fully coalesced 128B LDG per warp; W2[t] is 16 KB, L2-resident.
        // h1_s operand is a per-warp broadcast (same address on all lanes).
        {
            int h = tid & 63, j0 = tid >> 6;
            float s[8];
            float bb = b2t[h];
            #pragma unroll
            for (int k = 0; k < 8; k++) s[k] = bb;
            #pragma unroll 16
            for (int r = 0; r < 64; r++) {
                float w = W2t[r * 64 + h];
                #pragma unroll
                for (int k = 0; k < 8; k++)
                    s[k] = fmaf(h1_s[(j0 + 4 * k) * 64 + r], w, s[k]);
            }
            #pragma unroll
            for (int k = 0; k < 8; k++)
                h2_s[(j0 + 4 * k) * 64 + h] = siluf(s[k]);
        }
        __syncthreads();

        // ---- contracted tensor ctr[j][c*dd+d] (path-specific, cheap) ----
        for (int idx = tid; idx < 32 * md; idx += 256) {
            int j = idx / md, cd = idx - j * md;
            float v;
            if (t == 0) {
                int c = cd;
                v = e_s[j * 4] * f0n_s[j * 16 + c];
            } else if (t == 1) {
                int c = cd / 3, d = cd - c * 3;
                v = e_s[j * 4 + 1 + d] * f0n_s[j * 16 + c];
            } else if (t == 2) {
                int c = cd / 3, d = cd - c * 3;
                v = e_s[j * 4] * f1n_s[j * 48 + c * 3 + d];
            } else if (t == 3) {
                int c = cd;
                v = e_s[j * 4 + 1] * f1n_s[j * 48 + c * 3]
                  + e_s[j * 4 + 2] * f1n_s[j * 48 + c * 3 + 1]
                  + e_s[j * 4 + 3] * f1n_s[j * 48 + c * 3 + 2];
            } else {
                int c = cd / 3, d = cd - c * 3;
                int d1 = (d + 1) % 3, d2 = (d + 2) % 3;
                // (f1 x e1)_d
                v = f1n_s[j * 48 + c * 3 + d1] * e_s[j * 4 + 1 + d2]
                  - f1n_s[j * 48 + c * 3 + d2] * e_s[j * 4 + 1 + d1];
            }
            ctr_s[j * 48 + cd] = v;
        }
        __syncthreads();

        // ---- M[h][cd] = sum_j h2[j][h] * ctr[j][cd]  (h=64 row = bias row) ----
        {
            int h = tid >> 2, cq = tid & 3;
            int nc = md >> 2;          // 4 (dd=1) or 12 (dd=3)
            int cd0 = cq * nc;
            float s[12];
            #pragma unroll
            for (int m = 0; m < 12; m++) s[m] = 0.f;
            for (int j = 0; j < 32; j++) {
                float hv = h2_s[j * 64 + h];
                const float* cr = ctr_s + j * 48 + cd0;
                if (md == 48) {
                    #pragma unroll
                    for (int m = 0; m < 12; m += 4) {
                        float4 c4 = *(const float4*)&cr[m];
                        s[m + 0] = fmaf(hv, c4.x, s[m + 0]);
                        s[m + 1] = fmaf(hv, c4.y, s[m + 1]);
                        s[m + 2] = fmaf(hv, c4.z, s[m + 2]);
                        s[m + 3] = fmaf(hv, c4.w, s[m + 3]);
                    }
                } else {
                    float4 c4 = *(const float4*)&cr[0];
                    s[0] = fmaf(hv, c4.x, s[0]);
                    s[1] = fmaf(hv, c4.y, s[1]);
                    s[2] = fmaf(hv, c4.z, s[2]);
                    s[3] = fmaf(hv, c4.w, s[3]);
                }
            }
            if (md == 48) {
                #pragma unroll
                for (int m = 0; m < 12; m++) M_s[h * 48 + cd0 + m] = s[m];
            } else {
                #pragma unroll
                for (int m = 0; m < 4; m++) M_s[h * 48 + cd0 + m] = s[m];
            }
        }
        if (tid < md) {  // virtual bias row: sum_j ctr
            float s = 0.f;
            #pragma unroll 8
            for (int j = 0; j < 32; j++) s += ctr_s[j * 48 + tid];
            M_s[64 * 48 + tid] = s;
        }
        __syncthreads();

        // ---- msg[o][d] = sum_{h,c} M[h][c*dd+d] * W3[t,h,c*16+o] ----
        {
            int o = tid & 15, grp = tid >> 4;  // 16 h-groups of 4 rows
            float p0 = 0.f, p1 = 0.f, p2 = 0.f;
            #pragma unroll
            for (int hh = 0; hh < 4; hh++) {
                int h = grp * 4 + hh;
                const float* w3row = W3t + h * 256 + o;
                const float* mrow  = M_s + h * 48;
                #pragma unroll
                for (int c = 0; c < 16; c++) {
                    float w = w3row[c * 16];
                    if (dd == 1) {
                        p0 = fmaf(mrow[c], w, p0);
                    } else {
                        p0 = fmaf(mrow[c * 3 + 0], w, p0);
                        p1 = fmaf(mrow[c * 3 + 1], w, p1);
                        p2 = fmaf(mrow[c * 3 + 2], w, p2);
                    }
                }
            }
            if (grp == 0) {  // bias row (h=64), weight = b3
                const float* mrow = M_s + 64 * 48;
                #pragma unroll
                for (int c = 0; c < 16; c++) {
                    float w = b3t[c * 16 + o];
                    if (dd == 1) {
                        p0 = fmaf(mrow[c], w, p0);
                    } else {
                        p0 = fmaf(mrow[c * 3 + 0], w, p0);
                        p1 = fmaf(mrow[c * 3 + 1], w, p1);
                        p2 = fmaf(mrow[c * 3 + 2], w, p2);
                    }
                }
            }
            red_s[grp * 48 + o * dd + 0] = p0;
            if (dd == 3) {
                red_s[grp * 48 + o * dd + 1] = p1;
                red_s[grp * 48 + o * dd + 2] = p2;
            }
        }
        __syncthreads();
        if (tid < md) {
            float s = 0.f;
            #pragma unroll
            for (int g = 0; g < 16; g++) s += red_s[g * 48 + tid];
            if (ot == 0) acc0[tid] += s;
            else         acc1[tid] += s;   // tid == o*3+d
        }
        __syncthreads();
    }

    // ---- Post: type_norm, gates, residual ----
    float* nrm = red_s;        // 32
    float* f0g = red_s + 32;   // 16 (= normalized out0)
    float* o1n = red_s + 48;   // 48 (= normalized out1)
    float* g1s = red_s + 96;   // 16

    if (tid < 16) {
        nrm[tid] = fmaxf(fabsf(acc0[tid]), 1e-8f);
        float a = acc1[tid * 3], b = acc1[tid * 3 + 1], c = acc1[tid * 3 + 2];
        nrm[16 + tid] = fmaxf(sqrtf(a * a + b * b + c * c), 1e-8f);
    }
    __syncthreads();
    if (tid < 16) {
        float mu0 = 0.f, mu1 = 0.f;
        #pragma unroll
        for (int c = 0; c < 16; c++) { mu0 += nrm[c]; mu1 += nrm[16 + c]; }
        mu0 *= 0.0625f; mu1 *= 0.0625f;
        float v0 = 0.f, v1 = 0.f;
        #pragma unroll
        for (int c = 0; c < 16; c++) {
            float d0 = nrm[c] - mu0;      v0 += d0 * d0;
            float d1 = nrm[16 + c] - mu1; v1 += d1 * d1;
        }
        v0 *= 0.0625f; v1 *= 0.0625f;
        float sc0 = (nrm[tid] - mu0) * rsqrtf(v0 + 1e-5f) * ln_g0[tid] + ln_b0[tid];
        float sc1 = (nrm[16 + tid] - mu1) * rsqrtf(v1 + 1e-5f) * ln_g1[tid] + ln_b1[tid];
        f0g[tid] = acc0[tid] / nrm[tid] * sc0;
        float inv1 = sc1 / nrm[16 + tid];
        o1n[tid * 3 + 0] = acc1[tid * 3 + 0] * inv1;
        o1n[tid * 3 + 1] = acc1[tid * 3 + 1] * inv1;
        o1n[tid * 3 + 2] = acc1[tid * 3 + 2] * inv1;
    }
    __syncthreads();
    if (tid < 16) {
        float z0 = gate_b0[tid], z1 = gate_b1[tid];
        #pragma unroll
        for (int c = 0; c < 16; c++) {
            z0 = fmaf(f0g[c], gate_W0[c * 16 + tid], z0);
            z1 = fmaf(f0g[c], gate_W1[c * 16 + tid], z1);
        }
        float g0 = sigmf(z0);
        g1s[tid] = sigmf(z1);
        float r = 0.f;
        #pragma unroll
        for (int c = 0; c < 16; c++)
            r = fmaf(f0[i * 16 + c], res_W0[c * 16 + tid], r);
        out[i * 16 + tid] = f0g[tid] * g0 + r;
    }
    __syncthreads();
    if (tid < 48) {
        int o = tid / 3, d = tid - o * 3;
        float r = 0.f;
        #pragma unroll
        for (int c = 0; c < 16; c++)
            r = fmaf(f1[(i * 16 + c) * 3 + d], res_W1[c * 16 + o], r);
        out[NN * 16 + i * 48 + tid] = o1n[tid] * g1s[o] + r;
    }
}

extern "C" void kernel_launch(void* const* d_in, const int* in_sizes, int n_in,
                              void* d_out, int out_size)
{
    (void)in_sizes; (void)n_in; (void)out_size;
    const float* f0       = (const float*)d_in[0];
    const float* f1       = (const float*)d_in[1];
    const float* rbf      = (const float*)d_in[2];
    const float* gt_edge  = (const float*)d_in[3];
    const float* W1       = (const float*)d_in[4];
    const float* b1       = (const float*)d_in[5];
    const float* W2       = (const float*)d_in[6];
    const float* b2       = (const float*)d_in[7];
    const float* W3       = (const float*)d_in[8];
    const float* b3       = (const float*)d_in[9];
    const float* ln_g0    = (const float*)d_in[10];
    const float* ln_b0    = (const float*)d_in[11];
    const float* ln_g1    = (const float*)d_in[12];
    const float* ln_b1    = (const float*)d_in[13];
    const float* gate_W0  = (const float*)d_in[14];
    const float* gate_b0  = (const float*)d_in[15];
    const float* gate_W1  = (const float*)d_in[16];
    const float* gate_b1  = (const float*)d_in[17];
    const float* res_W0   = (const float*)d_in[18];
    const float* res_W1   = (const float*)d_in[19];
    const int* nbr        = (const int*)d_in[20];
    float* out = (float*)d_out;

    gtt_kernel<<<NN, 256, SMEM_BYTES>>>(f0, f1, rbf, gt_edge, W1, b1, W2, b2, W3, b3,
                                        ln_g0, ln_b0, ln_g1, ln_b1,
                                        gate_W0, gate_b0, gate_W1, gate_b1,
                                        res_W0, res_W1, nbr, out);
}

// round 11
// speedup vs baseline: 1.0334x; 1.0334x over previous
#include <cuda_runtime.h>
#include <cuda_bf16.h>

// Problem constants
#define NN   8192
#define KK   32
#define CC   16
#define RBFN 16
#define HH   64

// Dynamic shared-memory layout (in floats).
// Total dynamic = 12,272 floats = 49,088 B; static smem = 0.
// 49,088 <= 49,152 (48 KB default cap) -> legal without cudaFuncSetAttribute.
#define OFF_RBF  0        // 32*16  = 512
#define OFF_E    512      // 32*4   = 128
#define OFF_F0N  640      // 32*16  = 512
#define OFF_F1N  1152     // 32*48  = 1536
#define OFF_H1   2688     // 32*64  = 2048
#define OFF_H2   4736     // 32*64  = 2048
#define OFF_CTR  6784     // 32*48  = 1536
#define OFF_M    8320     // 65*48  = 3120   (nb_s aliases first 32 floats early)
#define OFF_RED  11440    // 16*48  = 768
#define OFF_ACC0 12208    // 16
#define OFF_ACC1 12224    // 48
#define SMEM_FLOATS 12272
#define SMEM_BYTES (SMEM_FLOATS * 4)

__device__ __forceinline__ float siluf(float x) {
    return __fdividef(x, 1.0f + __expf(-x));
}
__device__ __forceinline__ float sigmf(float x) {
    return __fdividef(1.0f, 1.0f + __expf(-x));
}

__global__ __launch_bounds__(256, 4)
void gtt_kernel(const float* __restrict__ f0, const float* __restrict__ f1,
                const float* __restrict__ rbf, const float* __restrict__ gt_edge,
                const float* __restrict__ W1, const float* __restrict__ b1,
                const float* __restrict__ W2, const float* __restrict__ b2,
                const float* __restrict__ W3, const float* __restrict__ b3,
                const float* __restrict__ ln_g0, const float* __restrict__ ln_b0,
                const float* __restrict__ ln_g1, const float* __restrict__ ln_b1,
                const float* __restrict__ gate_W0, const float* __restrict__ gate_b0,
                const float* __restrict__ gate_W1, const float* __restrict__ gate_b1,
                const float* __restrict__ res_W0, const float* __restrict__ res_W1,
                const int* __restrict__ nbr_idx,
                float* __restrict__ out)
{
    extern __shared__ float sm[];
    float* rbf_s = sm + OFF_RBF;
    float* e_s   = sm + OFF_E;
    float* f0n_s = sm + OFF_F0N;
    float* f1n_s = sm + OFF_F1N;
    float* h1_s  = sm + OFF_H1;
    float* h2_s  = sm + OFF_H2;
    float* ctr_s = sm + OFF_CTR;
    float* M_s   = sm + OFF_M;
    float* red_s = sm + OFF_RED;
    float* acc0  = sm + OFF_ACC0;
    float* acc1  = sm + OFF_ACC1;
    int*   nb_s  = (int*)(sm + OFF_M);   // aliases M_s; dead before M_s written

    const int tid = threadIdx.x;
    const int i   = blockIdx.x;

    // ---- Phase 1: node-local loads ----
    if (tid < KK) nb_s[tid] = nbr_idx[i * KK + tid];
    for (int idx = tid; idx < 512; idx += 256)
        rbf_s[idx] = rbf[i * 512 + idx];
    if (tid < 128) e_s[tid] = gt_edge[i * 128 + tid];
    if (tid < 64) { if (tid < 16) acc0[tid] = 0.f; else acc1[tid - 16] = 0.f; }
    __syncthreads();

    // ---- Phase 2: neighbor gathers ----
    for (int idx = tid; idx < 512; idx += 256) {
        int j = idx >> 4, c = idx & 15;
        f0n_s[idx] = f0[nb_s[j] * 16 + c];
    }
    for (int idx = tid; idx < 1536; idx += 256) {
        int j = idx / 48, r = idx - j * 48;
        f1n_s[idx] = f1[nb_s[j] * 48 + r];
    }
    __syncthreads();

    // ---- Interaction paths ----
    #pragma unroll
    for (int t = 0; t < 5; t++) {
        const int dd = (t == 0 || t == 3) ? 1 : 3;   // output vector dim
        const int ot = (t == 0 || t == 3) ? 0 : 1;   // which output accumulator
        const int md = 16 * dd;
        const float* W1t = W1 + t * RBFN * HH;
        const float* b1t = b1 + t * HH;
        const float* W2t = W2 + t * HH * HH;
        const float* b2t = b2 + t * HH;
        const float* W3t = W3 + t * HH * 256;
        const float* b3t = b3 + t * 256;

        // ---- h1 = silu(rbf @ W1 + b1) : [32 x 64] ----
        // float4 on rbf rows (contiguous in r); W1 scalar coalesced LDG.
        {
            int h = tid & 63, j0 = tid >> 6;
            float s[8];
            float bb = b1t[h];
            #pragma unroll
            for (int k = 0; k < 8; k++) s[k] = bb;
            #pragma unroll
            for (int rb = 0; rb < 4; rb++) {
                float w0 = W1t[(4 * rb + 0) * 64 + h];
                float w1 = W1t[(4 * rb + 1) * 64 + h];
                float w2 = W1t[(4 * rb + 2) * 64 + h];
                float w3v = W1t[(4 * rb + 3) * 64 + h];
                #pragma unroll
                for (int k = 0; k < 8; k++) {
                    float4 a = *(const float4*)&rbf_s[(j0 + 4 * k) * 16 + 4 * rb];
                    s[k] = fmaf(a.x, w0, s[k]);
                    s[k] = fmaf(a.y, w1, s[k]);
                    s[k] = fmaf(a.z, w2, s[k]);
                    s[k] = fmaf(a.w, w3v, s[k]);
                }
            }
            #pragma unroll
            for (int k = 0; k < 8; k++)
                h1_s[(j0 + 4 * k) * 64 + h] = siluf(s[k]);
        }
        __syncthreads();

        // ---- h2 = silu(h1 @ W2 + b2) : [32 x 64] ----
        // float4 on h1 rows (4 consecutive r); W2 scalar coalesced LDG (L2-hot).
        {
            int h = tid & 63, j0 = tid >> 6;
            float s[8];
            float bb = b2t[h];
            #pragma unroll
            for (int k = 0; k < 8; k++) s[k] = bb;
            #pragma unroll
            for (int hb = 0; hb < 16; hb++) {
                float w0 = W2t[(4 * hb + 0) * 64 + h];
                float w1 = W2t[(4 * hb + 1) * 64 + h];
                float w2 = W2t[(4 * hb + 2) * 64 + h];
                float w3v = W2t[(4 * hb + 3) * 64 + h];
                #pragma unroll
                for (int k = 0; k < 8; k++) {
                    float4 a = *(const float4*)&h1_s[(j0 + 4 * k) * 64 + 4 * hb];
                    s[k] = fmaf(a.x, w0, s[k]);
                    s[k] = fmaf(a.y, w1, s[k]);
                    s[k] = fmaf(a.z, w2, s[k]);
                    s[k] = fmaf(a.w, w3v, s[k]);
                }
            }
            #pragma unroll
            for (int k = 0; k < 8; k++)
                h2_s[(j0 + 4 * k) * 64 + h] = siluf(s[k]);
        }
        __syncthreads();

        // ---- contracted tensor ctr[j][c*dd+d] (path-specific, cheap) ----
        for (int idx = tid; idx < 32 * md; idx += 256) {
            int j = idx / md, cd = idx - j * md;
            float v;
            if (t == 0) {
                int c = cd;
                v = e_s[j * 4] * f0n_s[j * 16 + c];
            } else if (t == 1) {
                int c = cd / 3, d = cd - c * 3;
                v = e_s[j * 4 + 1 + d] * f0n_s[j * 16 + c];
            } else if (t == 2) {
                int c = cd / 3, d = cd - c * 3;
                v = e_s[j * 4] * f1n_s[j * 48 + c * 3 + d];
            } else if (t == 3) {
                int c = cd;
                v = e_s[j * 4 + 1] * f1n_s[j * 48 + c * 3]
                  + e_s[j * 4 + 2] * f1n_s[j * 48 + c * 3 + 1]
                  + e_s[j * 4 + 3] * f1n_s[j * 48 + c * 3 + 2];
            } else {
                int c = cd / 3, d = cd - c * 3;
                int d1 = (d + 1) % 3, d2 = (d + 2) % 3;
                v = f1n_s[j * 48 + c * 3 + d1] * e_s[j * 4 + 1 + d2]
                  - f1n_s[j * 48 + c * 3 + d2] * e_s[j * 4 + 1 + d1];
            }
            ctr_s[j * 48 + cd] = v;
        }
        __syncthreads();

        // ---- M[h][cd] = sum_j h2[j][h] * ctr[j][cd]  (h=64 row = bias row) ----
        {
            int h = tid >> 2, cq = tid & 3;
            int nc = md >> 2;          // 4 (dd=1) or 12 (dd=3)
            int cd0 = cq * nc;
            float s[12];
            #pragma unroll
            for (int m = 0; m < 12; m++) s[m] = 0.f;
            for (int j = 0; j < 32; j++) {
                float hv = h2_s[j * 64 + h];
                const float* cr = ctr_s + j * 48 + cd0;
                if (md == 48) {
                    #pragma unroll
                    for (int m = 0; m < 12; m += 4) {
                        float4 c4 = *(const float4*)&cr[m];
                        s[m + 0] = fmaf(hv, c4.x, s[m + 0]);
                        s[m + 1] = fmaf(hv, c4.y, s[m + 1]);
                        s[m + 2] = fmaf(hv, c4.z, s[m + 2]);
                        s[m + 3] = fmaf(hv, c4.w, s[m + 3]);
                    }
                } else {
                    float4 c4 = *(const float4*)&cr[0];
                    s[0] = fmaf(hv, c4.x, s[0]);
                    s[1] = fmaf(hv, c4.y, s[1]);
                    s[2] = fmaf(hv, c4.z, s[2]);
                    s[3] = fmaf(hv, c4.w, s[3]);
                }
            }
            if (md == 48) {
                #pragma unroll
                for (int m = 0; m < 12; m++) M_s[h * 48 + cd0 + m] = s[m];
            } else {
                #pragma unroll
                for (int m = 0; m < 4; m++) M_s[h * 48 + cd0 + m] = s[m];
            }
        }
        if (tid < md) {  // virtual bias row: sum_j ctr
            float s = 0.f;
            #pragma unroll 8
            for (int j = 0; j < 32; j++) s += ctr_s[j * 48 + tid];
            M_s[64 * 48 + tid] = s;
        }
        __syncthreads();

        // ---- msg[o][d] = sum_{h,c} M[h][c*dd+d] * W3[t,h,c*16+o] ----
        // W3 weights hoisted to registers per h-row; M rows read as float4 with
        // compile-time (c,d) decomposition of each component.
        {
            int o = tid & 15, grp = tid >> 4;
            float p0 = 0.f, p1 = 0.f, p2 = 0.f;

            #define GTT_ACC(vv, idx) do {                       \
                const int c_ = (idx) / 3, d_ = (idx) % 3;       \
                if (d_ == 0)      p0 = fmaf((vv), w[c_], p0);   \
                else if (d_ == 1) p1 = fmaf((vv), w[c_], p1);   \
                else              p2 = fmaf((vv), w[c_], p2);   \
            } while (0)

            #pragma unroll
            for (int hh = 0; hh < 4; hh++) {
                int h = grp * 4 + hh;
                const float* w3row = W3t + h * 256 + o;
                float w[16];
                #pragma unroll
                for (int c = 0; c < 16; c++) w[c] = w3row[c * 16];
                const float4* m4 = (const float4*)(M_s + h * 48);
                if (dd == 1) {
                    #pragma unroll
                    for (int q = 0; q < 4; q++) {
                        float4 m = m4[q];
                        p0 = fmaf(m.x, w[4 * q + 0], p0);
                        p0 = fmaf(m.y, w[4 * q + 1], p0);
                        p0 = fmaf(m.z, w[4 * q + 2], p0);
                        p0 = fmaf(m.w, w[4 * q + 3], p0);
                    }
                } else {
                    #pragma unroll
                    for (int q = 0; q < 12; q++) {
                        float4 m = m4[q];
                        GTT_ACC(m.x, 4 * q + 0);
                        GTT_ACC(m.y, 4 * q + 1);
                        GTT_ACC(m.z, 4 * q + 2);
                        GTT_ACC(m.w, 4 * q + 3);
                    }
                }
            }
            if (grp == 0) {  // bias row (h=64), weight = b3
                float w[16];
                #pragma unroll
                for (int c = 0; c < 16; c++) w[c] = b3t[c * 16 + o];
                const float4* m4 = (const float4*)(M_s + 64 * 48);
                if (dd == 1) {
                    #pragma unroll
                    for (int q = 0; q < 4; q++) {
                        float4 m = m4[q];
                        p0 = fmaf(m.x, w[4 * q + 0], p0);
                        p0 = fmaf(m.y, w[4 * q + 1], p0);
                        p0 = fmaf(m.z, w[4 * q + 2], p0);
                        p0 = fmaf(m.w, w[4 * q + 3], p0);
                    }
                } else {
                    #pragma unroll
                    for (int q = 0; q < 12; q++) {
                        float4 m = m4[q];
                        GTT_ACC(m.x, 4 * q + 0);
                        GTT_ACC(m.y, 4 * q + 1);
                        GTT_ACC(m.z, 4 * q + 2);
                        GTT_ACC(m.w, 4 * q + 3);
                    }
                }
            }
            #undef GTT_ACC

            red_s[grp * 48 + o * dd + 0] = p0;
            if (dd == 3) {
                red_s[grp * 48 + o * dd + 1] = p1;
                red_s[grp * 48 + o * dd + 2] = p2;
            }
        }
        __syncthreads();
        if (tid < md) {
            float s = 0.f;
            #pragma unroll
            for (int g = 0; g < 16; g++) s += red_s[g * 48 + tid];
            if (ot == 0) acc0[tid] += s;
            else         acc1[tid] += s;
        }
        __syncthreads();
    }

    // ---- Post: type_norm, gates, residual ----
    float* nrm = red_s;        // 32
    float* f0g = red_s + 32;   // 16
    float* o1n = red_s + 48;   // 48
    float* g1s = red_s + 96;   // 16

    if (tid < 16) {
        nrm[tid] = fmaxf(fabsf(acc0[tid]), 1e-8f);
        float a = acc1[tid * 3], b = acc1[tid * 3 + 1], c = acc1[tid * 3 + 2];
        nrm[16 + tid] = fmaxf(sqrtf(a * a + b * b + c * c), 1e-8f);
    }
    __syncthreads();
    if (tid < 16) {
        float mu0 = 0.f, mu1 = 0.f;
        #pragma unroll
        for (int c = 0; c < 16; c++) { mu0 += nrm[c]; mu1 += nrm[16 + c]; }
        mu0 *= 0.0625f; mu1 *= 0.0625f;
        float v0 = 0.f, v1 = 0.f;
        #pragma unroll
        for (int c = 0; c < 16; c++) {
            float d0 = nrm[c] - mu0;      v0 += d0 * d0;
            float d1 = nrm[16 + c] - mu1; v1 += d1 * d1;
        }
        v0 *= 0.0625f; v1 *= 0.0625f;
        float sc0 = (nrm[tid] - mu0) * rsqrtf(v0 + 1e-5f) * ln_g0[tid] + ln_b0[tid];
        float sc1 = (nrm[16 + tid] - mu1) * rsqrtf(v1 + 1e-5f) * ln_g1[tid] + ln_b1[tid];
        f0g[tid] = acc0[tid] / nrm[tid] * sc0;
        float inv1 = sc1 / nrm[16 + tid];
        o1n[tid * 3 + 0] = acc1[tid * 3 + 0] * inv1;
        o1n[tid * 3 + 1] = acc1[tid * 3 + 1] * inv1;
        o1n[tid * 3 + 2] = acc1[tid * 3 + 2] * inv1;
    }
    __syncthreads();
    if (tid < 16) {
        float z0 = gate_b0[tid], z1 = gate_b1[tid];
        #pragma unroll
        for (int c = 0; c < 16; c++) {
            z0 = fmaf(f0g[c], gate_W0[c * 16 + tid], z0);
            z1 = fmaf(f0g[c], gate_W1[c * 16 + tid], z1);
        }
        float g0 = sigmf(z0);
        g1s[tid] = sigmf(z1);
        float r = 0.f;
        #pragma unroll
        for (int c = 0; c < 16; c++)
            r = fmaf(f0[i * 16 + c], res_W0[c * 16 + tid], r);
        out[i * 16 + tid] = f0g[tid] * g0 + r;
    }
    __syncthreads();
    if (tid < 48) {
        int o = tid / 3, d = tid - o * 3;
        float r = 0.f;
        #pragma unroll
        for (int c = 0; c < 16; c++)
            r = fmaf(f1[(i * 16 + c) * 3 + d], res_W1[c * 16 + o], r);
        out[NN * 16 + i * 48 + tid] = o1n[tid] * g1s[o] + r;
    }
}

extern "C" void kernel_launch(void* const* d_in, const int* in_sizes, int n_in,
                              void* d_out, int out_size)
{
    (void)in_sizes; (void)n_in; (void)out_size;
    const float* f0       = (const float*)d_in[0];
    const float* f1       = (const float*)d_in[1];
    const float* rbf      = (const float*)d_in[2];
    const float* gt_edge  = (const float*)d_in[3];
    const float* W1       = (const float*)d_in[4];
    const float* b1       = (const float*)d_in[5];
    const float* W2       = (const float*)d_in[6];
    const float* b2       = (const float*)d_in[7];
    const float* W3       = (const float*)d_in[8];
    const float* b3       = (const float*)d_in[9];
    const float* ln_g0    = (const float*)d_in[10];
    const float* ln_b0    = (const float*)d_in[11];
    const float* ln_g1    = (const float*)d_in[12];
    const float* ln_b1    = (const float*)d_in[13];
    const float* gate_W0  = (const float*)d_in[14];
    const float* gate_b0  = (const float*)d_in[15];
    const float* gate_W1  = (const float*)d_in[16];
    const float* gate_b1  = (const float*)d_in[17];
    const float* res_W0   = (const float*)d_in[18];
    const float* res_W1   = (const float*)d_in[19];
    const int* nbr        = (const int*)d_in[20];
    float* out = (float*)d_out;

    gtt_kernel<<<NN, 256, SMEM_BYTES>>>(f0, f1, rbf, gt_edge, W1, b1, W2, b2, W3, b3,
                                        ln_g0, ln_b0, ln_g1, ln_b1,
                                        gate_W0, gate_b0, gate_W1, gate_b1,
                                        res_W0, res_W1, nbr, out);
}